// round 6
// baseline (speedup 1.0000x reference)
#include <cuda_runtime.h>
#include <cuda_bf16.h>
#include <mma.h>
#include <cstdint>

using namespace nvcuda;

#define NN 50000
#define EE 800000
#define CC 128
#define SA 132              // padded smem row stride for fp32 activations (floats)
#define NTHR 512
#define NT_EDGE (EE/128)    // 6250 edge tiles

#define WSTR 136            // bf16 weight/act leading dim (elements)
#define CSTR 132            // fp32 C leading dim
#define WHALF_BYTES (128*WSTR*2)       // 34816 one bf16 matrix image
#define SLOT_BYTES  (2*WHALF_BYTES)    // hi+lo 69632
#define ACT_OFF     (2*SLOT_BYTES)     // 139264: act-hi, act-lo / C fp32 overlay
#define IDX_OFF     (ACT_OFF + SLOT_BYTES)  // 208896
#define SM_EDGE3    (IDX_OFF + 1024)   // 209920

// ---------------- scratch (__device__ globals: allocation-free) ----------------
__device__ __align__(16) float g_q[(size_t)NN*CC];    // qa1 = h @ (W_dst@aw1)
__device__ __align__(16) float g_k[(size_t)NN*CC];    // ka1 = h @ (W_src@aw1)
__device__ __align__(16) float g_v[(size_t)NN*CC];
__device__ __align__(16) float g_pw[(size_t)NN*CC];   // posW1 = pos @ pw1
__device__ __align__(16) float g_z[(size_t)NN*CC];
__device__ __align__(16) float g_num[(size_t)NN*CC];
__device__ __align__(16) float g_Wqa[CC*CC];          // W_dst @ aw1
__device__ __align__(16) float g_Wka[CC*CC];          // W_src @ aw1
// pre-split bf16 hi/lo images of {pw2, aw1, aw2}, padded ld=136
__device__ __align__(16) __nv_bfloat16 g_wsp[3*2*128*WSTR];
__device__ int g_is64;

// ---------------- packed f32x2 helpers (node/out kernels) ----------------
__device__ __forceinline__ unsigned long long pk2(float lo, float hi){
  unsigned long long r;
  asm("mov.b64 %0, {%1,%2};" : "=l"(r) : "f"(lo), "f"(hi));
  return r;
}
__device__ __forceinline__ float2 up2(unsigned long long v){
  float2 f;
  asm("mov.b64 {%0,%1}, %2;" : "=f"(f.x), "=f"(f.y) : "l"(v));
  return f;
}
__device__ __forceinline__ void fma2(unsigned long long &d, unsigned long long a, unsigned long long b){
  asm("fma.rn.f32x2 %0, %1, %2, %0;" : "+l"(d) : "l"(a), "l"(b));
}

// ---------------- FFMA2 128x128x128 tile GEMM (node/out kernels) ----------------
__device__ __forceinline__ void gemm_tile(const float* __restrict__ As,
                                          const float* __restrict__ Ws,
                                          int m0, int cb,
                                          unsigned long long acc[4][4]){
  #pragma unroll
  for (int i=0;i<4;i++)
    #pragma unroll
    for (int j=0;j<4;j++) acc[i][j] = 0ULL;

  #pragma unroll 2
  for (int k4=0;k4<CC;k4+=4){
    float4 a4[4];
    #pragma unroll
    for (int i=0;i<4;i++) a4[i] = *(const float4*)(As + (m0+i)*SA + k4);
    #pragma unroll
    for (int kk=0;kk<4;kk++){
      const float* wr = Ws + (k4+kk)*CC + cb;
      unsigned long long w[4];
      #pragma unroll
      for (int j=0;j<4;j++) w[j] = *(const unsigned long long*)(wr + 32*j);
      #pragma unroll
      for (int i=0;i<4;i++){
        float a = (kk==0)?a4[i].x:(kk==1)?a4[i].y:(kk==2)?a4[i].z:a4[i].w;
        unsigned long long ad = pk2(a,a);
        #pragma unroll
        for (int j=0;j<4;j++) fma2(acc[i][j], ad, w[j]);
      }
    }
  }
}

__device__ __forceinline__ void load_w128(float* Ws, const float* __restrict__ W, int tid){
  #pragma unroll
  for (int i = tid; i < CC*CC/4; i += NTHR)
    ((float4*)Ws)[i] = ((const float4*)W)[i];
}
__device__ __forceinline__ void load_a128(float* As, const float* __restrict__ A, int tid){
  #pragma unroll
  for (int i = tid; i < CC*32; i += NTHR){
    int r = i >> 5, c4 = i & 31;
    *(float4*)(As + r*SA + 4*c4) = ((const float4*)A)[i];
  }
}
__device__ __forceinline__ void epi_relu_smem(unsigned long long acc[4][4],
                                              const float* __restrict__ bias,
                                              float* Bs, int m0, int cb){
  #pragma unroll
  for (int i=0;i<4;i++){
    #pragma unroll
    for (int j=0;j<4;j++){
      int c = cb + 32*j;
      float2 p = up2(acc[i][j]);
      float2 b = *(const float2*)(bias + c);
      float2 o;
      o.x = fmaxf(p.x + b.x, 0.f);
      o.y = fmaxf(p.y + b.y, 0.f);
      *(float2*)(Bs + (m0+i)*SA + c) = o;
    }
  }
}
__device__ __forceinline__ void store_plain(unsigned long long acc[4][4],
                                            float* out, int r0, int m0, int cb){
  #pragma unroll
  for (int i=0;i<4;i++){
    int r = r0 + m0 + i;
    if (r < NN){
      #pragma unroll
      for (int j=0;j<4;j++)
        *(float2*)(out + (size_t)r*CC + cb + 32*j) = up2(acc[i][j]);
    }
  }
}

// ---------------- cp.async helpers ----------------
__device__ __forceinline__ void cp16(void* sdst, const void* gsrc){
  unsigned s = (unsigned)__cvta_generic_to_shared(sdst);
  asm volatile("cp.async.cg.shared.global [%0], [%1], 16;" :: "r"(s), "l"(gsrc));
}
// copy one weight slot (hi+lo, 69632B) from pre-split global image
__device__ __forceinline__ void cp_slot(char* smc, int s, int w, int tid){
  const char* src = (const char*)g_wsp + (size_t)w * SLOT_BYTES;
  char* dst = smc + s * SLOT_BYTES;
  #pragma unroll
  for (int i = tid; i < SLOT_BYTES/16; i += NTHR)
    cp16(dst + 16*i, src + 16*i);
  asm volatile("cp.async.commit_group;");
}
#define CPWAIT1 asm volatile("cp.async.wait_group 1;")
#define CPWAIT0 asm volatile("cp.async.wait_group 0;")

// ---------------- detect edge_index element width ----------------
__global__ void detect_kernel(const void* __restrict__ ei){
  const unsigned long long* p = (const unsigned long long*)ei;
  int ok64 = 1;
  for (int i=0;i<64;i++){
    if ((p[i] >> 32) != 0ULL){ ok64 = 0; break; }
  }
  g_is64 = ok64;
}

// ---------------- weight split kernel: fp32 -> bf16 hi/lo padded images ----------------
__global__ void wsplit_kernel(const float* __restrict__ pw2,
                              const float* __restrict__ aw1,
                              const float* __restrict__ aw2){
  const float* W = (blockIdx.x==0) ? pw2 : (blockIdx.x==1) ? aw1 : aw2;
  __nv_bfloat16* hi = g_wsp + (size_t)blockIdx.x * 2 * 128 * WSTR;
  __nv_bfloat16* lo = hi + 128*WSTR;
  for (int i = threadIdx.x; i < 128*128; i += blockDim.x){
    int k = i >> 7, n = i & 127;
    float w = W[i];
    __nv_bfloat16 h = __float2bfloat16(w);
    hi[k*WSTR + n] = h;
    lo[k*WSTR + n] = __float2bfloat16(w - __bfloat162float(h));
  }
}

// ---------------- composite weight kernel ----------------
#define SM_COMP (CC*SA*4 + CC*CC*4)
__global__ void __launch_bounds__(NTHR,1)
comp_kernel(const float* __restrict__ W_dst, const float* __restrict__ W_src,
            const float* __restrict__ aw1){
  extern __shared__ float sm[];
  float* As = sm;
  float* Ws = sm + CC*SA;
  int tid = threadIdx.x;
  int tx = tid & 15, ty = tid >> 4;
  int m0 = ty*4, cb = 2*tx;
  const float* A = blockIdx.x ? W_src : W_dst;
  float* out = blockIdx.x ? g_Wka : g_Wqa;

  load_a128(As, A, tid);
  load_w128(Ws, aw1, tid);
  __syncthreads();
  unsigned long long acc[4][4];
  gemm_tile(As, Ws, m0, cb, acc);
  #pragma unroll
  for (int i=0;i<4;i++)
    #pragma unroll
    for (int j=0;j<4;j++)
      *(float2*)(out + (m0+i)*CC + cb + 32*j) = up2(acc[i][j]);
}

// ---------------- node kernel: h, v, qa1, ka1, posW1 ----------------
#define SM_NODE (2*CC*SA*4 + CC*CC*4)
__global__ void __launch_bounds__(NTHR,1)
node_kernel(const float* __restrict__ x, const float* __restrict__ pos,
            const float* __restrict__ W_in, const float* __restrict__ b_in,
            const float* __restrict__ W_lin, const float* __restrict__ pw1){
  extern __shared__ float sm[];
  float* As = sm;
  float* Bs = sm + CC*SA;
  float* Ws = sm + 2*CC*SA;
  int tid = threadIdx.x;
  int tx = tid & 15, ty = tid >> 4;
  int m0 = ty*4, cb = 2*tx;
  int r0 = blockIdx.x * 128;

  load_w128(Ws, W_in, tid);
  #pragma unroll 1
  for (int i = tid; i < CC*32; i += NTHR){
    int r = i >> 5, c4 = i & 31;
    float4 v = make_float4(0.f,0.f,0.f,0.f);
    if (r0 + r < NN) v = *((const float4*)(x + (size_t)(r0+r)*CC) + c4);
    *(float4*)(As + r*SA + 4*c4) = v;
  }
  __syncthreads();

  unsigned long long acc[4][4];
  gemm_tile(As, Ws, m0, cb, acc);
  __syncthreads();
  epi_relu_smem(acc, b_in, Bs, m0, cb);     // h
  load_w128(Ws, W_lin, tid);
  __syncthreads();

  gemm_tile(Bs, Ws, m0, cb, acc);           // v
  store_plain(acc, g_v, r0, m0, cb);
  __syncthreads();
  load_w128(Ws, g_Wqa, tid);
  __syncthreads();

  gemm_tile(Bs, Ws, m0, cb, acc);           // qa1
  store_plain(acc, g_q, r0, m0, cb);
  __syncthreads();
  load_w128(Ws, g_Wka, tid);
  __syncthreads();

  gemm_tile(Bs, Ws, m0, cb, acc);           // ka1
  store_plain(acc, g_k, r0, m0, cb);
  __syncthreads();

  load_w128(Ws, pw1, tid);
  #pragma unroll 1
  for (int i = tid; i < CC*32; i += NTHR){
    int r = i >> 5, c4 = i & 31;
    float4 v = make_float4(0.f,0.f,0.f,0.f);
    if (r0 + r < NN) v = *((const float4*)(pos + (size_t)(r0+r)*CC) + c4);
    *(float4*)(As + r*SA + 4*c4) = v;
  }
  __syncthreads();

  gemm_tile(As, Ws, m0, cb, acc);           // posW1
  store_plain(acc, g_pw, r0, m0, cb);
}

// ---------------- wmma edge GEMM: C(128x128) = [Ahi+Alo] @ [Whi+Wlo], 3-term ----------------
// 16 warps: wr = wid&7 (16-row band), wc = wid>>3 (64-col band).
__device__ __forceinline__ void gemm_store(const char* smc, int slot,
                                           int wr, int wc){
  const __nv_bfloat16* Ahi = (const __nv_bfloat16*)(smc + ACT_OFF);
  const __nv_bfloat16* Alo = Ahi + 128*WSTR;
  const __nv_bfloat16* Whi = (const __nv_bfloat16*)(smc + slot*SLOT_BYTES);
  const __nv_bfloat16* Wlo = Whi + 128*WSTR;
  float* Csm = (float*)(smc + ACT_OFF);

  wmma::fragment<wmma::accumulator,16,16,16,float> c[4];
  #pragma unroll
  for (int n=0;n<4;n++) wmma::fill_fragment(c[n], 0.f);

  #pragma unroll 1
  for (int k0=0;k0<8;k0++){
    wmma::fragment<wmma::matrix_a,16,16,16,__nv_bfloat16,wmma::row_major> ah, al;
    wmma::load_matrix_sync(ah, Ahi + (wr*16)*WSTR + k0*16, WSTR);
    wmma::load_matrix_sync(al, Alo + (wr*16)*WSTR + k0*16, WSTR);
    #pragma unroll
    for (int n=0;n<4;n++){
      wmma::fragment<wmma::matrix_b,16,16,16,__nv_bfloat16,wmma::row_major> bh, bl;
      wmma::load_matrix_sync(bh, Whi + (k0*16)*WSTR + wc*64 + n*16, WSTR);
      wmma::load_matrix_sync(bl, Wlo + (k0*16)*WSTR + wc*64 + n*16, WSTR);
      wmma::mma_sync(c[n], ah, bh, c[n]);
      wmma::mma_sync(c[n], al, bh, c[n]);
      wmma::mma_sync(c[n], ah, bl, c[n]);
    }
  }
  __syncthreads();   // all warps done reading act + this weight slot
  #pragma unroll
  for (int n=0;n<4;n++)
    wmma::store_matrix_sync(Csm + (wr*16)*CSTR + wc*64 + n*16, c[n], CSTR,
                            wmma::mem_row_major);
}

// split 32 fp32 -> bf16 hi/lo act rows
__device__ __forceinline__ void write_act(char* smc, int r, int c0, const float* v){
  __nv_bfloat16* Ahi = (__nv_bfloat16*)(smc + ACT_OFF);
  __nv_bfloat16* Alo = Ahi + 128*WSTR;
  #pragma unroll
  for (int j=0;j<16;j++){
    float x = v[2*j], y = v[2*j+1];
    __nv_bfloat16 hx = __float2bfloat16(x), hy = __float2bfloat16(y);
    __nv_bfloat162 hp = __halves2bfloat162(hx, hy);
    __nv_bfloat162 lp = __halves2bfloat162(
        __float2bfloat16(x - __bfloat162float(hx)),
        __float2bfloat16(y - __bfloat162float(hy)));
    *(__nv_bfloat162*)(Ahi + r*WSTR + c0 + 2*j) = hp;
    *(__nv_bfloat162*)(Alo + r*WSTR + c0 + 2*j) = lp;
  }
}

// ---------------- persistent edge kernel (HMMA path) ----------------
__global__ void __launch_bounds__(NTHR,1)
edge_kernel(const void* __restrict__ ei,
            const float* __restrict__ pb1, const float* __restrict__ pb2,
            const float* __restrict__ ab1, const float* __restrict__ ab2){
  extern __shared__ char smc[];
  int tid = threadIdx.x;
  int wid = tid >> 5;
  int wr = wid & 7, wc = wid >> 3;
  int r = tid >> 2;                 // epilogue row
  int c0 = (tid & 3) * 32;          // epilogue col base
  int* si = (int*)(smc + IDX_OFF);
  int* di = si + 128;
  float* Csm = (float*)(smc + ACT_OFF);

  int cur = 0;
  cp_slot(smc, cur, 0, tid);        // pw2 -> slot0   pending:{pw2}

  for (int t = blockIdx.x; t < NT_EDGE; t += gridDim.x){
    long long e0 = (long long)t * 128;
    __syncthreads();                // prev tile epi done with Csm/idx
    if (tid < 128){
      if (g_is64){
        const long long* p = (const long long*)ei;
        si[tid] = (int)p[e0 + tid];
        di[tid] = (int)p[(long long)EE + e0 + tid];
      } else {
        const int* p = (const int*)ei;
        si[tid] = p[e0 + tid];
        di[tid] = p[(long long)EE + e0 + tid];
      }
    }
    cp_slot(smc, cur^1, 1, tid);    // aw1           pending:{pw2,aw1}
    __syncthreads();
    int sdx = si[r], ddx = di[r];
    float dlt[32];

    // ---- phase A: act = relu(posW1[dst]-posW1[src]+pb1) ----
    {
      const float4* pd = (const float4*)(g_pw + (size_t)ddx*CC + c0);
      const float4* ps = (const float4*)(g_pw + (size_t)sdx*CC + c0);
      const float4* pb = (const float4*)(pb1 + c0);
      float v[32];
      #pragma unroll
      for (int q=0;q<8;q++){
        float4 a = pd[q], b = ps[q], bb = __ldg(pb + q);
        v[4*q]   = fmaxf(a.x - b.x + bb.x, 0.f);
        v[4*q+1] = fmaxf(a.y - b.y + bb.y, 0.f);
        v[4*q+2] = fmaxf(a.z - b.z + bb.z, 0.f);
        v[4*q+3] = fmaxf(a.w - b.w + bb.w, 0.f);
      }
      write_act(smc, r, c0, v);
    }
    CPWAIT1;                        // pw2 arrived   pending:{aw1}
    __syncthreads();

    gemm_store(smc, cur, wr, wc);   // GEMM1 @pw2 -> Csm
    cp_slot(smc, cur, 2, tid);      // aw2           pending:{aw1,aw2}
    __syncthreads();                // Csm visible

    // ---- epi1: delta = relu(C + pb2), keep in regs ----
    {
      const float4* pb = (const float4*)(pb2 + c0);
      #pragma unroll
      for (int q=0;q<8;q++){
        float4 cv = *(const float4*)(Csm + r*CSTR + c0 + 4*q);
        float4 bb = __ldg(pb + q);
        dlt[4*q]   = fmaxf(cv.x + bb.x, 0.f);
        dlt[4*q+1] = fmaxf(cv.y + bb.y, 0.f);
        dlt[4*q+2] = fmaxf(cv.z + bb.z, 0.f);
        dlt[4*q+3] = fmaxf(cv.w + bb.w, 0.f);
      }
    }
    __syncthreads();                // C reads done before act overwrite
    write_act(smc, r, c0, dlt);
    CPWAIT1;                        // aw1 arrived   pending:{aw2}
    __syncthreads();

    gemm_store(smc, cur^1, wr, wc); // GEMM2 @aw1 -> Csm
    cp_slot(smc, cur^1, 0, tid);    // next tile pw2 pending:{aw2,pw2'}
    __syncthreads();

    // ---- epi2: attn_in = relu(C + qa1[dst]-ka1[src]+ab1) ----
    {
      const float4* qr = (const float4*)(g_q + (size_t)ddx*CC + c0);
      const float4* kr = (const float4*)(g_k + (size_t)sdx*CC + c0);
      const float4* ab = (const float4*)(ab1 + c0);
      float v[32];
      #pragma unroll
      for (int q=0;q<8;q++){
        float4 cv = *(const float4*)(Csm + r*CSTR + c0 + 4*q);
        float4 qv = qr[q], kv = kr[q], bb = __ldg(ab + q);
        v[4*q]   = fmaxf(cv.x + qv.x - kv.x + bb.x, 0.f);
        v[4*q+1] = fmaxf(cv.y + qv.y - kv.y + bb.y, 0.f);
        v[4*q+2] = fmaxf(cv.z + qv.z - kv.z + bb.z, 0.f);
        v[4*q+3] = fmaxf(cv.w + qv.w - kv.w + bb.w, 0.f);
      }
      __syncthreads();
      write_act(smc, r, c0, v);
    }
    CPWAIT1;                        // aw2 arrived   pending:{pw2'}
    __syncthreads();

    gemm_store(smc, cur, wr, wc);   // GEMM3 @aw2 -> Csm
    __syncthreads();

    // ---- epi3: ea = exp(relu(C+ab2)); num += ea*(v[src]+delta); z += ea ----
    {
      const float4* ab = (const float4*)(ab2 + c0);
      const float4* vr = (const float4*)(g_v + (size_t)sdx*CC + c0);
      float* zp = g_z   + (size_t)ddx*CC + c0;
      float* np = g_num + (size_t)ddx*CC + c0;
      #pragma unroll
      for (int q=0;q<8;q++){
        float4 cv = *(const float4*)(Csm + r*CSTR + c0 + 4*q);
        float4 bb = __ldg(ab + q);
        float4 vv = vr[q];
        // alpha >= 0 and small: softmax without max-subtraction is exact here
        float e0f = __expf(fmaxf(cv.x + bb.x, 0.f));
        float e1f = __expf(fmaxf(cv.y + bb.y, 0.f));
        float e2f = __expf(fmaxf(cv.z + bb.z, 0.f));
        float e3f = __expf(fmaxf(cv.w + bb.w, 0.f));
        float p0 = e0f * (vv.x + dlt[4*q]);
        float p1 = e1f * (vv.y + dlt[4*q+1]);
        float p2 = e2f * (vv.z + dlt[4*q+2]);
        float p3 = e3f * (vv.w + dlt[4*q+3]);
        asm volatile("red.global.add.v4.f32 [%0], {%1,%2,%3,%4};"
                     :: "l"(zp + 4*q), "f"(e0f),"f"(e1f),"f"(e2f),"f"(e3f) : "memory");
        asm volatile("red.global.add.v4.f32 [%0], {%1,%2,%3,%4};"
                     :: "l"(np + 4*q), "f"(p0),"f"(p1),"f"(p2),"f"(p3) : "memory");
      }
    }
    cur ^= 1;
  }
  CPWAIT0;
}

// ---------------- output kernel: agg = num/z ; out = relu(agg W_out + b_out) ----------------
#define SM_OUT (CC*SA*4 + CC*CC*4)
__global__ void __launch_bounds__(NTHR,1)
out_kernel(const float* __restrict__ W_out, const float* __restrict__ b_out,
           float* __restrict__ out){
  extern __shared__ float sm[];
  float* As = sm;
  float* Ws = sm + CC*SA;
  int tid = threadIdx.x;
  int tx = tid & 15, ty = tid >> 4;
  int m0 = ty*4, cb = 2*tx;
  int r0 = blockIdx.x * 128;

  load_w128(Ws, W_out, tid);
  #pragma unroll 1
  for (int i = tid; i < CC*32; i += NTHR){
    int r = i >> 5, c4 = i & 31;
    float4 a = make_float4(0.f,0.f,0.f,0.f);
    if (r0 + r < NN){
      float4 nm = *((const float4*)(g_num + (size_t)(r0+r)*CC) + c4);
      float4 zz = *((const float4*)(g_z   + (size_t)(r0+r)*CC) + c4);
      a.x = nm.x / (zz.x + 1e-16f);
      a.y = nm.y / (zz.y + 1e-16f);
      a.z = nm.z / (zz.z + 1e-16f);
      a.w = nm.w / (zz.w + 1e-16f);
    }
    *(float4*)(As + r*SA + 4*c4) = a;
  }
  __syncthreads();

  unsigned long long acc[4][4];
  gemm_tile(As, Ws, m0, cb, acc);

  #pragma unroll
  for (int i=0;i<4;i++){
    int r = r0 + m0 + i;
    if (r < NN){
      #pragma unroll
      for (int j=0;j<4;j++){
        int c = cb + 32*j;
        float2 p = up2(acc[i][j]);
        float2 bb = *(const float2*)(b_out + c);
        float2 o;
        o.x = fmaxf(p.x + bb.x, 0.f);
        o.y = fmaxf(p.y + bb.y, 0.f);
        *(float2*)(out + (size_t)r*CC + c) = o;
      }
    }
  }
}

// ---------------- launch ----------------
extern "C" void kernel_launch(void* const* d_in, const int* in_sizes, int n_in,
                              void* d_out, int out_size){
  const float* x    = (const float*)d_in[0];
  const float* pos  = (const float*)d_in[1];
  const void*  ei   = d_in[2];
  const float* W_in = (const float*)d_in[3];
  const float* b_in = (const float*)d_in[4];
  const float* W_lin= (const float*)d_in[5];
  const float* W_src= (const float*)d_in[6];
  const float* W_dst= (const float*)d_in[7];
  const float* pw1  = (const float*)d_in[8];
  const float* pb1  = (const float*)d_in[9];
  const float* pw2  = (const float*)d_in[10];
  const float* pb2  = (const float*)d_in[11];
  const float* aw1  = (const float*)d_in[12];
  const float* ab1  = (const float*)d_in[13];
  const float* aw2  = (const float*)d_in[14];
  const float* ab2  = (const float*)d_in[15];
  const float* W_out= (const float*)d_in[16];
  const float* b_out= (const float*)d_in[17];

  static int nsm = 0;
  if (!nsm){
    cudaDeviceGetAttribute(&nsm, cudaDevAttrMultiProcessorCount, 0);
    if (nsm <= 0) nsm = 148;
    cudaFuncSetAttribute(comp_kernel, cudaFuncAttributeMaxDynamicSharedMemorySize, SM_COMP);
    cudaFuncSetAttribute(node_kernel, cudaFuncAttributeMaxDynamicSharedMemorySize, SM_NODE);
    cudaFuncSetAttribute(edge_kernel, cudaFuncAttributeMaxDynamicSharedMemorySize, SM_EDGE3);
    cudaFuncSetAttribute(out_kernel,  cudaFuncAttributeMaxDynamicSharedMemorySize, SM_OUT);
  }

  void *zp = nullptr, *np = nullptr;
  cudaGetSymbolAddress(&zp, g_z);
  cudaGetSymbolAddress(&np, g_num);
  cudaMemsetAsync(zp, 0, (size_t)NN*CC*sizeof(float), 0);
  cudaMemsetAsync(np, 0, (size_t)NN*CC*sizeof(float), 0);

  detect_kernel<<<1, 1>>>(ei);
  wsplit_kernel<<<3, NTHR>>>(pw2, aw1, aw2);
  comp_kernel<<<2, NTHR, SM_COMP>>>(W_dst, W_src, aw1);
  node_kernel<<<(NN+127)/128, NTHR, SM_NODE>>>(x, pos, W_in, b_in, W_lin, pw1);
  edge_kernel<<<nsm, NTHR, SM_EDGE3>>>(ei, pb1, pb2, ab1, ab2);
  out_kernel<<<(NN+127)/128, NTHR, SM_OUT>>>(W_out, b_out, (float*)d_out);
}

// round 7
// speedup vs baseline: 1.1142x; 1.1142x over previous
#include <cuda_runtime.h>
#include <cstdint>

#define NN 50000
#define EE 800000
#define CC 128
#define SA 132              // padded smem row stride for activations (floats)
#define NTHR 512
#define NTHR_E 1024
#define NT_EDGE (EE/128)    // 6250 edge tiles

// ---------------- scratch (__device__ globals: allocation-free) ----------------
__device__ __align__(16) float g_q[(size_t)NN*CC];    // qa1 = h @ (W_dst@aw1)
__device__ __align__(16) float g_k[(size_t)NN*CC];    // ka1 = h @ (W_src@aw1)
__device__ __align__(16) float g_v[(size_t)NN*CC];
__device__ __align__(16) float g_pw[(size_t)NN*CC];   // posW1 = pos @ pw1
__device__ __align__(16) float g_z[(size_t)NN*CC];
__device__ __align__(16) float g_num[(size_t)NN*CC];
__device__ __align__(16) float g_Wqa[CC*CC];          // W_dst @ aw1
__device__ __align__(16) float g_Wka[CC*CC];          // W_src @ aw1
__device__ int g_is64;

// ---------------- packed f32x2 helpers ----------------
__device__ __forceinline__ unsigned long long pk2(float lo, float hi){
  unsigned long long r;
  asm("mov.b64 %0, {%1,%2};" : "=l"(r) : "f"(lo), "f"(hi));
  return r;
}
__device__ __forceinline__ float2 up2(unsigned long long v){
  float2 f;
  asm("mov.b64 {%0,%1}, %2;" : "=f"(f.x), "=f"(f.y) : "l"(v));
  return f;
}
__device__ __forceinline__ void fma2(unsigned long long &d, unsigned long long a, unsigned long long b){
  asm("fma.rn.f32x2 %0, %1, %2, %0;" : "+l"(d) : "l"(a), "l"(b));
}

// ---------------- cp.async helpers ----------------
__device__ __forceinline__ void cp16(float* sdst, const float* gsrc){
  unsigned s = (unsigned)__cvta_generic_to_shared(sdst);
  asm volatile("cp.async.cg.shared.global [%0], [%1], 16;" :: "r"(s), "l"(gsrc));
}
__device__ __forceinline__ void cpw_async(float* dst, const float* __restrict__ src,
                                          int tid, int nthr){
  #pragma unroll
  for (int i = tid; i < CC*CC/4; i += nthr) cp16(dst + 4*i, src + 4*i);
  asm volatile("cp.async.commit_group;");
}
#define CPWAIT1 asm volatile("cp.async.wait_group 1;")
#define CPWAIT0 asm volatile("cp.async.wait_group 0;")

// ---------------- FFMA2 tile GEMM for node/out (512thr: 4 rows x 4 col-pairs) ----------------
__device__ __forceinline__ void gemm_tile(const float* __restrict__ As,
                                          const float* __restrict__ Ws,
                                          int m0, int cb,
                                          unsigned long long acc[4][4]){
  #pragma unroll
  for (int i=0;i<4;i++)
    #pragma unroll
    for (int j=0;j<4;j++) acc[i][j] = 0ULL;

  #pragma unroll 2
  for (int k4=0;k4<CC;k4+=4){
    float4 a4[4];
    #pragma unroll
    for (int i=0;i<4;i++) a4[i] = *(const float4*)(As + (m0+i)*SA + k4);
    #pragma unroll
    for (int kk=0;kk<4;kk++){
      const float* wr = Ws + (k4+kk)*CC + cb;
      unsigned long long w[4];
      #pragma unroll
      for (int j=0;j<4;j++) w[j] = *(const unsigned long long*)(wr + 32*j);
      #pragma unroll
      for (int i=0;i<4;i++){
        float a = (kk==0)?a4[i].x:(kk==1)?a4[i].y:(kk==2)?a4[i].z:a4[i].w;
        unsigned long long ad = pk2(a,a);
        #pragma unroll
        for (int j=0;j<4;j++) fma2(acc[i][j], ad, w[j]);
      }
    }
  }
}

// ---------------- FFMA2 tile GEMM for edge (1024thr: 4 rows x 2 col-pairs) ----------------
__device__ __forceinline__ void gemm_tile_e(const float* __restrict__ As,
                                            const float* __restrict__ Ws,
                                            int m0, int cb,
                                            unsigned long long acc[4][2]){
  #pragma unroll
  for (int i=0;i<4;i++){
    acc[i][0] = 0ULL; acc[i][1] = 0ULL;
  }
  #pragma unroll 2
  for (int k4=0;k4<CC;k4+=4){
    float4 a4[4];
    #pragma unroll
    for (int i=0;i<4;i++) a4[i] = *(const float4*)(As + (m0+i)*SA + k4);
    #pragma unroll
    for (int kk=0;kk<4;kk++){
      const float* wr = Ws + (k4+kk)*CC + cb;
      unsigned long long w0 = *(const unsigned long long*)(wr);
      unsigned long long w1 = *(const unsigned long long*)(wr + 32);
      #pragma unroll
      for (int i=0;i<4;i++){
        float a = (kk==0)?a4[i].x:(kk==1)?a4[i].y:(kk==2)?a4[i].z:a4[i].w;
        unsigned long long ad = pk2(a,a);
        fma2(acc[i][0], ad, w0);
        fma2(acc[i][1], ad, w1);
      }
    }
  }
}

__device__ __forceinline__ void load_w128(float* Ws, const float* __restrict__ W, int tid){
  #pragma unroll
  for (int i = tid; i < CC*CC/4; i += NTHR)
    ((float4*)Ws)[i] = ((const float4*)W)[i];
}
__device__ __forceinline__ void load_a128(float* As, const float* __restrict__ A, int tid){
  #pragma unroll
  for (int i = tid; i < CC*32; i += NTHR){
    int r = i >> 5, c4 = i & 31;
    *(float4*)(As + r*SA + 4*c4) = ((const float4*)A)[i];
  }
}
__device__ __forceinline__ void epi_relu_smem(unsigned long long acc[4][4],
                                              const float* __restrict__ bias,
                                              float* Bs, int m0, int cb){
  #pragma unroll
  for (int i=0;i<4;i++){
    #pragma unroll
    for (int j=0;j<4;j++){
      int c = cb + 32*j;
      float2 p = up2(acc[i][j]);
      float2 b = *(const float2*)(bias + c);
      float2 o;
      o.x = fmaxf(p.x + b.x, 0.f);
      o.y = fmaxf(p.y + b.y, 0.f);
      *(float2*)(Bs + (m0+i)*SA + c) = o;
    }
  }
}
__device__ __forceinline__ void store_plain(unsigned long long acc[4][4],
                                            float* out, int r0, int m0, int cb){
  #pragma unroll
  for (int i=0;i<4;i++){
    int r = r0 + m0 + i;
    if (r < NN){
      #pragma unroll
      for (int j=0;j<4;j++)
        *(float2*)(out + (size_t)r*CC + cb + 32*j) = up2(acc[i][j]);
    }
  }
}

// ---------------- detect edge_index element width ----------------
__global__ void detect_kernel(const void* __restrict__ ei){
  const unsigned long long* p = (const unsigned long long*)ei;
  int ok64 = 1;
  for (int i=0;i<64;i++){
    if ((p[i] >> 32) != 0ULL){ ok64 = 0; break; }
  }
  g_is64 = ok64;
}

// ---------------- composite weight kernel: g_Wqa = W_dst@aw1, g_Wka = W_src@aw1 ----------------
#define SM_COMP (CC*SA*4 + CC*CC*4)
__global__ void __launch_bounds__(NTHR,1)
comp_kernel(const float* __restrict__ W_dst, const float* __restrict__ W_src,
            const float* __restrict__ aw1){
  extern __shared__ float sm[];
  float* As = sm;
  float* Ws = sm + CC*SA;
  int tid = threadIdx.x;
  int tx = tid & 15, ty = tid >> 4;
  int m0 = ty*4, cb = 2*tx;
  const float* A = blockIdx.x ? W_src : W_dst;
  float* out = blockIdx.x ? g_Wka : g_Wqa;

  load_a128(As, A, tid);
  load_w128(Ws, aw1, tid);
  __syncthreads();
  unsigned long long acc[4][4];
  gemm_tile(As, Ws, m0, cb, acc);
  #pragma unroll
  for (int i=0;i<4;i++)
    #pragma unroll
    for (int j=0;j<4;j++)
      *(float2*)(out + (m0+i)*CC + cb + 32*j) = up2(acc[i][j]);
}

// ---------------- node kernel: h, v, qa1, ka1, posW1 ----------------
#define SM_NODE (2*CC*SA*4 + CC*CC*4)
__global__ void __launch_bounds__(NTHR,1)
node_kernel(const float* __restrict__ x, const float* __restrict__ pos,
            const float* __restrict__ W_in, const float* __restrict__ b_in,
            const float* __restrict__ W_lin, const float* __restrict__ pw1){
  extern __shared__ float sm[];
  float* As = sm;
  float* Bs = sm + CC*SA;
  float* Ws = sm + 2*CC*SA;
  int tid = threadIdx.x;
  int tx = tid & 15, ty = tid >> 4;
  int m0 = ty*4, cb = 2*tx;
  int r0 = blockIdx.x * 128;

  load_w128(Ws, W_in, tid);
  #pragma unroll 1
  for (int i = tid; i < CC*32; i += NTHR){
    int r = i >> 5, c4 = i & 31;
    float4 v = make_float4(0.f,0.f,0.f,0.f);
    if (r0 + r < NN) v = *((const float4*)(x + (size_t)(r0+r)*CC) + c4);
    *(float4*)(As + r*SA + 4*c4) = v;
  }
  __syncthreads();

  unsigned long long acc[4][4];
  gemm_tile(As, Ws, m0, cb, acc);           // x @ W_in
  __syncthreads();
  epi_relu_smem(acc, b_in, Bs, m0, cb);     // h
  load_w128(Ws, W_lin, tid);
  __syncthreads();

  gemm_tile(Bs, Ws, m0, cb, acc);           // v
  store_plain(acc, g_v, r0, m0, cb);
  __syncthreads();
  load_w128(Ws, g_Wqa, tid);
  __syncthreads();

  gemm_tile(Bs, Ws, m0, cb, acc);           // qa1
  store_plain(acc, g_q, r0, m0, cb);
  __syncthreads();
  load_w128(Ws, g_Wka, tid);
  __syncthreads();

  gemm_tile(Bs, Ws, m0, cb, acc);           // ka1
  store_plain(acc, g_k, r0, m0, cb);
  __syncthreads();

  load_w128(Ws, pw1, tid);
  #pragma unroll 1
  for (int i = tid; i < CC*32; i += NTHR){
    int r = i >> 5, c4 = i & 31;
    float4 v = make_float4(0.f,0.f,0.f,0.f);
    if (r0 + r < NN) v = *((const float4*)(pos + (size_t)(r0+r)*CC) + c4);
    *(float4*)(As + r*SA + 4*c4) = v;
  }
  __syncthreads();

  gemm_tile(As, Ws, m0, cb, acc);           // posW1
  store_plain(acc, g_pw, r0, m0, cb);
}

// ---------------- persistent edge kernel: 1024 threads, 3 GEMMs + softmax-numerator ----------------
// Warp map: half = wid>>4 selects 64-col block; wrow = wid&15 selects 8-row block;
// lane: lr = lane>>4 picks 4-row subblock, lc = lane&15 picks col pair base.
// Each thread: rows m0..m0+3, col pairs {cb, cb+32}. Conflict-free LDS; coalesced global.
#define SM_EDGE (2*CC*CC*4 + CC*SA*4 + 1024)
__global__ void __launch_bounds__(NTHR_E,1)
edge_kernel(const void* __restrict__ ei,
            const float* __restrict__ pb1, const float* __restrict__ pw2,
            const float* __restrict__ pb2,
            const float* __restrict__ aw1, const float* __restrict__ ab1,
            const float* __restrict__ aw2, const float* __restrict__ ab2){
  extern __shared__ float sm[];
  float* WB0 = sm;
  float* WB1 = sm + CC*CC;
  float* As  = sm + 2*CC*CC;
  int* si = (int*)(As + CC*SA);
  int* di = si + 128;
  int tid = threadIdx.x;
  int wid = tid >> 5, lane = tid & 31;
  int half = wid >> 4, wrow = wid & 15;
  int lr = lane >> 4, lc = lane & 15;
  int m0 = wrow*8 + lr*4;
  int cb = half*64 + lc*2;

  float* WB[2] = {WB0, WB1};

  cpw_async(WB[0], pw2, tid, NTHR_E);   // prologue; pending:{pw2}
  int it = 0;

  for (int t = blockIdx.x; t < NT_EDGE; t += gridDim.x, it++){
    int b = it & 1;                     // pw2 lives in WB[b] this tile
    long long e0 = (long long)t * 128;

    __syncthreads();                    // prev tile done with As/si/di
    if (tid < 128){
      if (g_is64){
        const long long* p = (const long long*)ei;
        si[tid] = (int)p[e0 + tid];
        di[tid] = (int)p[(long long)EE + e0 + tid];
      } else {
        const int* p = (const int*)ei;
        si[tid] = p[e0 + tid];
        di[tid] = p[(long long)EE + e0 + tid];
      }
    }
    cpw_async(WB[b^1], aw1, tid, NTHR_E);   // pending:{pw2,aw1}
    CPWAIT1;                                // pw2 arrived
    __syncthreads();                        // publish idx

    // phase A: As = relu(posW1[dst] - posW1[src] + pb1)
    #pragma unroll 1
    for (int i = tid; i < CC*32; i += NTHR_E){
      int e = i >> 5, c4 = i & 31;
      float4 a = *((const float4*)(g_pw + (size_t)di[e]*CC) + c4);
      float4 bch = *((const float4*)(g_pw + (size_t)si[e]*CC) + c4);
      float4 bb = __ldg((const float4*)(pb1) + c4);
      float4 o;
      o.x = fmaxf(a.x - bch.x + bb.x, 0.f);
      o.y = fmaxf(a.y - bch.y + bb.y, 0.f);
      o.z = fmaxf(a.z - bch.z + bb.z, 0.f);
      o.w = fmaxf(a.w - bch.w + bb.w, 0.f);
      *(float4*)(As + e*SA + 4*c4) = o;
    }
    __syncthreads();                        // As + pw2 ready

    unsigned long long acc[4][2];
    gemm_tile_e(As, WB[b], m0, cb, acc);    // GEMM1: @pw2
    __syncthreads();                        // GEMM1 readers done

    // epi1: delta = relu(acc + pb2) -> regs + As (in place)
    float2 dlt[4][2];
    #pragma unroll
    for (int i=0;i<4;i++){
      #pragma unroll
      for (int j=0;j<2;j++){
        int c = cb + 32*j;
        float2 p = up2(acc[i][j]);
        float2 bb = *(const float2*)(pb2 + c);
        dlt[i][j].x = fmaxf(p.x + bb.x, 0.f);
        dlt[i][j].y = fmaxf(p.y + bb.y, 0.f);
        *(float2*)(As + (m0+i)*SA + c) = dlt[i][j];
      }
    }
    cpw_async(WB[b], aw2, tid, NTHR_E);     // pending:{aw1,aw2}
    CPWAIT1;                                // aw1 arrived
    __syncthreads();

    gemm_tile_e(As, WB[b^1], m0, cb, acc);  // GEMM2: delta @ aw1
    __syncthreads();                        // GEMM2 readers done

    // epi2: As = relu(acc + qa1[dst] - ka1[src] + ab1)
    #pragma unroll
    for (int i=0;i<4;i++){
      int m = m0 + i;
      const float* qr = g_q + (size_t)di[m]*CC;
      const float* kr = g_k + (size_t)si[m]*CC;
      #pragma unroll
      for (int j=0;j<2;j++){
        int c = cb + 32*j;
        float2 p = up2(acc[i][j]);
        float2 qv = *(const float2*)(qr + c);
        float2 kv = *(const float2*)(kr + c);
        float2 bb = *(const float2*)(ab1 + c);
        float2 o;
        o.x = fmaxf(p.x + qv.x - kv.x + bb.x, 0.f);
        o.y = fmaxf(p.y + qv.y - kv.y + bb.y, 0.f);
        *(float2*)(As + m*SA + c) = o;
      }
    }
    cpw_async(WB[b^1], pw2, tid, NTHR_E);   // next tile; pending:{aw2,pw2'}
    CPWAIT1;                                // aw2 arrived
    __syncthreads();

    gemm_tile_e(As, WB[b], m0, cb, acc);    // GEMM3: @aw2

    // epi3: ea = exp(relu(acc+ab2)); num += ea*(v[src]+delta); z += ea
    #pragma unroll
    for (int i=0;i<4;i++){
      int m = m0 + i;
      int sdx = si[m], ddx = di[m];
      const float* vr = g_v + (size_t)sdx*CC;
      float* zp = g_z   + (size_t)ddx*CC;
      float* np = g_num + (size_t)ddx*CC;
      #pragma unroll
      for (int j=0;j<2;j++){
        int c = cb + 32*j;
        float2 a2 = up2(acc[i][j]);
        float2 bb = *(const float2*)(ab2 + c);
        float al0 = fmaxf(a2.x + bb.x, 0.f);
        float al1 = fmaxf(a2.y + bb.y, 0.f);
        // alpha >= 0 and small: softmax without max-subtraction is exact here
        float ex0 = __expf(al0), ex1 = __expf(al1);
        float2 vv = *(const float2*)(vr + c);
        float p0 = ex0 * (vv.x + dlt[i][j].x);
        float p1 = ex1 * (vv.y + dlt[i][j].y);
        asm volatile("red.global.add.v2.f32 [%0], {%1,%2};"
                     :: "l"(zp + c), "f"(ex0), "f"(ex1) : "memory");
        asm volatile("red.global.add.v2.f32 [%0], {%1,%2};"
                     :: "l"(np + c), "f"(p0), "f"(p1) : "memory");
      }
    }
  }
  CPWAIT0;
}

// ---------------- output kernel: agg = num/z ; out = relu(agg W_out + b_out) ----------------
#define SM_OUT (CC*SA*4 + CC*CC*4)
__global__ void __launch_bounds__(NTHR,1)
out_kernel(const float* __restrict__ W_out, const float* __restrict__ b_out,
           float* __restrict__ out){
  extern __shared__ float sm[];
  float* As = sm;
  float* Ws = sm + CC*SA;
  int tid = threadIdx.x;
  int tx = tid & 15, ty = tid >> 4;
  int m0 = ty*4, cb = 2*tx;
  int r0 = blockIdx.x * 128;

  load_w128(Ws, W_out, tid);
  #pragma unroll 1
  for (int i = tid; i < CC*32; i += NTHR){
    int r = i >> 5, c4 = i & 31;
    float4 a = make_float4(0.f,0.f,0.f,0.f);
    if (r0 + r < NN){
      float4 nm = *((const float4*)(g_num + (size_t)(r0+r)*CC) + c4);
      float4 zz = *((const float4*)(g_z   + (size_t)(r0+r)*CC) + c4);
      a.x = nm.x / (zz.x + 1e-16f);
      a.y = nm.y / (zz.y + 1e-16f);
      a.z = nm.z / (zz.z + 1e-16f);
      a.w = nm.w / (zz.w + 1e-16f);
    }
    *(float4*)(As + r*SA + 4*c4) = a;
  }
  __syncthreads();

  unsigned long long acc[4][4];
  gemm_tile(As, Ws, m0, cb, acc);

  #pragma unroll
  for (int i=0;i<4;i++){
    int r = r0 + m0 + i;
    if (r < NN){
      #pragma unroll
      for (int j=0;j<4;j++){
        int c = cb + 32*j;
        float2 p = up2(acc[i][j]);
        float2 bb = *(const float2*)(b_out + c);
        float2 o;
        o.x = fmaxf(p.x + bb.x, 0.f);
        o.y = fmaxf(p.y + bb.y, 0.f);
        *(float2*)(out + (size_t)r*CC + c) = o;
      }
    }
  }
}

// ---------------- launch ----------------
extern "C" void kernel_launch(void* const* d_in, const int* in_sizes, int n_in,
                              void* d_out, int out_size){
  const float* x    = (const float*)d_in[0];
  const float* pos  = (const float*)d_in[1];
  const void*  ei   = d_in[2];
  const float* W_in = (const float*)d_in[3];
  const float* b_in = (const float*)d_in[4];
  const float* W_lin= (const float*)d_in[5];
  const float* W_src= (const float*)d_in[6];
  const float* W_dst= (const float*)d_in[7];
  const float* pw1  = (const float*)d_in[8];
  const float* pb1  = (const float*)d_in[9];
  const float* pw2  = (const float*)d_in[10];
  const float* pb2  = (const float*)d_in[11];
  const float* aw1  = (const float*)d_in[12];
  const float* ab1  = (const float*)d_in[13];
  const float* aw2  = (const float*)d_in[14];
  const float* ab2  = (const float*)d_in[15];
  const float* W_out= (const float*)d_in[16];
  const float* b_out= (const float*)d_in[17];

  static int nsm = 0;
  if (!nsm){
    cudaDeviceGetAttribute(&nsm, cudaDevAttrMultiProcessorCount, 0);
    if (nsm <= 0) nsm = 148;
    cudaFuncSetAttribute(comp_kernel, cudaFuncAttributeMaxDynamicSharedMemorySize, SM_COMP);
    cudaFuncSetAttribute(node_kernel, cudaFuncAttributeMaxDynamicSharedMemorySize, SM_NODE);
    cudaFuncSetAttribute(edge_kernel, cudaFuncAttributeMaxDynamicSharedMemorySize, SM_EDGE);
    cudaFuncSetAttribute(out_kernel,  cudaFuncAttributeMaxDynamicSharedMemorySize, SM_OUT);
  }

  void *zp = nullptr, *np = nullptr;
  cudaGetSymbolAddress(&zp, g_z);
  cudaGetSymbolAddress(&np, g_num);
  cudaMemsetAsync(zp, 0, (size_t)NN*CC*sizeof(float), 0);
  cudaMemsetAsync(np, 0, (size_t)NN*CC*sizeof(float), 0);

  detect_kernel<<<1, 1>>>(ei);
  comp_kernel<<<2, NTHR, SM_COMP>>>(W_dst, W_src, aw1);
  node_kernel<<<(NN+127)/128, NTHR, SM_NODE>>>(x, pos, W_in, b_in, W_lin, pw1);
  edge_kernel<<<nsm, NTHR_E, SM_EDGE>>>(ei, pb1, pw2, pb2, aw1, ab1, aw2, ab2);
  out_kernel<<<(NN+127)/128, NTHR, SM_OUT>>>(W_out, b_out, (float*)d_out);
}